// round 4
// baseline (speedup 1.0000x reference)
#include <cuda_runtime.h>

// ---------------- problem constants ----------------
#define D1     4096     // V of graph 1
#define V2n    2048     // V of graph 2
#define BN     64       // batch
#define K1     25
#define K2     25
#define F1     32       // CL1_F
#define F2     64       // CL2_F
#define NNZ1   32768
#define NNZ2   16384
#define CH2    2048     // F1*BN columns of conv2 state
#define FC1F   512
#define FC2F   10
#define FC1FIN 65536    // F2 * (D1/4)
#define KSPLIT 32       // split-K for fc1
// coef = 2/lmax = 1.0 exactly (folded into the math below)

// ---------------- device scratch (static; no runtime alloc) ----------------
__device__ int   g_cnt1[D1];
__device__ int   g_rp1[D1 + 1];
__device__ int   g_cur1[D1];
__device__ int   g_ci1[NNZ1];
__device__ float g_cv1[NNZ1];

__device__ int   g_cnt2[V2n];
__device__ int   g_rp2[V2n + 1];
__device__ int   g_cur2[V2n];
__device__ int   g_ci2[NNZ2];
__device__ float g_cv2[NNZ2];

__device__ float g_T1[K1 * D1 * BN];            // 6.55M floats, Cheby states conv1 [k][v][b]
__device__ float g_T2[K2 * V2n * CH2];          // 104.86M floats (400MB), conv2 states [k][v][fin*64+b]
__device__ float g_W2t[K2 * F1 * F2];           // transposed cl2_W: [k][fin][f]
__device__ float g_P[BN * FC1FIN];              // pooled conv2 out, [b][vp*64+f]
__device__ float g_fc1p[KSPLIT * BN * FC1F];    // fc1 split-K partials
__device__ float g_fc1[BN * FC1F];              // fc1 output (post relu)

// ---------------- f32x2 packed FMA (Blackwell FFMA2, PTX-only) ----------------
__device__ __forceinline__ float2 ffma2(float2 a, float2 b, float2 c) {
    float2 d;
    asm("fma.rn.f32x2 %0, %1, %2, %3;"
        : "=l"(reinterpret_cast<unsigned long long&>(d))
        : "l"(reinterpret_cast<unsigned long long&>(a)),
          "l"(reinterpret_cast<unsigned long long&>(b)),
          "l"(reinterpret_cast<unsigned long long&>(c)));
    return d;
}

// ---------------- CSR build ----------------
__global__ void k_zero() {
    int i = blockIdx.x * blockDim.x + threadIdx.x;
    if (i < D1)  g_cnt1[i] = 0;
    if (i < V2n) g_cnt2[i] = 0;
}

__global__ void k_count(const int* __restrict__ r1, const int* __restrict__ r2) {
    int i = blockIdx.x * blockDim.x + threadIdx.x;
    if (i < NNZ1) atomicAdd(&g_cnt1[r1[i]], 1);
    if (i < NNZ2) atomicAdd(&g_cnt2[r2[i]], 1);
}

__global__ void k_scan(int which) {
    __shared__ int s[1024];
    const int* cnt = which ? g_cnt2 : g_cnt1;
    int V  = which ? V2n : D1;
    int* rp  = which ? g_rp2  : g_rp1;
    int* cur = which ? g_cur2 : g_cur1;
    int tid = threadIdx.x;
    int per = V >> 10;          // 4 (graph1) or 2 (graph2)
    int base = tid * per;
    int loc[4];
    int sum = 0;
    for (int i = 0; i < per; i++) { loc[i] = cnt[base + i]; sum += loc[i]; }
    s[tid] = sum; __syncthreads();
    for (int off = 1; off < 1024; off <<= 1) {
        int v = (tid >= off) ? s[tid - off] : 0;
        __syncthreads();
        s[tid] += v;
        __syncthreads();
    }
    int run = (tid == 0) ? 0 : s[tid - 1];
    for (int i = 0; i < per; i++) { rp[base + i] = run; cur[base + i] = run; run += loc[i]; }
    if (tid == 1023) rp[V] = run;
}

__global__ void k_scatter(const int* __restrict__ rows, const int* __restrict__ cols,
                          const float* __restrict__ vals, int nnz, int which) {
    int i = blockIdx.x * blockDim.x + threadIdx.x;
    if (i >= nnz) return;
    int* cur  = which ? g_cur2 : g_cur1;
    int* ci   = which ? g_ci2  : g_ci1;
    float* cv = which ? g_cv2  : g_cv1;
    int p = atomicAdd(&cur[rows[i]], 1);
    ci[p] = cols[i];
    cv[p] = vals[i];
}

// ---------------- conv1: Chebyshev recurrence on [4096 x 64] ----------------
__global__ void k_t1_init(const float* __restrict__ x) {
    int idx = blockIdx.x * blockDim.x + threadIdx.x;   // < D1*BN
    int v = idx >> 6, b = idx & 63;
    g_T1[idx] = x[b * D1 + v];                          // x0[v][b] = x[b][v][0]
}

__global__ void k_cheb1(int k) {
    int tid = threadIdx.x;
    int v = blockIdx.x * 4 + (tid >> 6);
    int b = tid & 63;
    const float* Tm1 = g_T1 + (k - 1) * (D1 * BN);
    float acc = 0.f;
    int e1 = g_rp1[v + 1];
    for (int e = g_rp1[v]; e < e1; e++)
        acc = fmaf(g_cv1[e], Tm1[g_ci1[e] * BN + b], acc);
    float ls = acc - Tm1[v * BN + b];                   // coef = 1
    float out = (k >= 2) ? (2.f * ls - g_T1[(k - 2) * (D1 * BN) + v * BN + b]) : ls;
    g_T1[k * (D1 * BN) + v * BN + b] = out;
}

// conv1 GEMM (W1 [32,25]) + bias + relu + maxpool2 -> writes T2 slice 0 in [v2][fin*64+b] layout
__global__ void k_conv1_out(const float* __restrict__ W1, const float* __restrict__ b1) {
    __shared__ float sW[F1 * K1];
    __shared__ float sb[F1];
    int tid = threadIdx.x;
    for (int i = tid; i < F1 * K1; i += 256) sW[i] = W1[i];
    if (tid < F1) sb[tid] = b1[tid];
    __syncthreads();
    int v2 = blockIdx.x * 4 + (tid >> 6);
    int b  = tid & 63;
    float t0[K1], t1[K1];
#pragma unroll
    for (int k = 0; k < K1; k++) {
        t0[k] = g_T1[k * (D1 * BN) + (2 * v2) * BN + b];
        t1[k] = g_T1[k * (D1 * BN) + (2 * v2 + 1) * BN + b];
    }
    for (int f = 0; f < F1; f++) {
        float a0 = sb[f], a1 = sb[f];
#pragma unroll
        for (int k = 0; k < K1; k++) {
            float w = sW[f * K1 + k];
            a0 = fmaf(t0[k], w, a0);
            a1 = fmaf(t1[k], w, a1);
        }
        float o = fmaxf(fmaxf(a0, a1), 0.f);
        g_T2[v2 * CH2 + f * BN + b] = o;
    }
}

// ---------------- conv2: Chebyshev recurrence on [2048 x 2048] ----------------
__global__ void k_cheb2(int k) {
    __shared__ int   sci[128];
    __shared__ float scv[128];
    int v = blockIdx.x, tid = threadIdx.x;
    const float* Tm1 = g_T2 + (size_t)(k - 1) * V2n * CH2;
    float* out = g_T2 + (size_t)k * V2n * CH2 + (size_t)v * CH2;
    float acc[8] = {0.f, 0.f, 0.f, 0.f, 0.f, 0.f, 0.f, 0.f};
    int e0 = g_rp2[v], e1 = g_rp2[v + 1];
    for (int eb = e0; eb < e1; eb += 128) {
        int n = min(128, e1 - eb);
        if (tid < n) { sci[tid] = g_ci2[eb + tid]; scv[tid] = g_cv2[eb + tid]; }
        __syncthreads();
        for (int j = 0; j < n; j++) {
            const float* zr = Tm1 + (size_t)sci[j] * CH2 + tid;
            float w = scv[j];
#pragma unroll
            for (int i = 0; i < 8; i++) acc[i] = fmaf(w, zr[i * 256], acc[i]);
        }
        __syncthreads();
    }
    const float* z1r = Tm1 + (size_t)v * CH2;
    if (k >= 2) {
        const float* z0r = g_T2 + (size_t)(k - 2) * V2n * CH2 + (size_t)v * CH2;
#pragma unroll
        for (int i = 0; i < 8; i++) {
            int c = tid + i * 256;
            out[c] = 2.f * (acc[i] - z1r[c]) - z0r[c];
        }
    } else {
#pragma unroll
        for (int i = 0; i < 8; i++) {
            int c = tid + i * 256;
            out[c] = acc[i] - z1r[c];
        }
    }
}

// transpose cl2_W [64][fin*25+k] -> g_W2t[k][fin][f]
__global__ void k_w2t(const float* __restrict__ W2) {
    int i = blockIdx.x * blockDim.x + threadIdx.x;
    if (i < K2 * F1 * F2) {
        int f   = i & 63;
        int fin = (i >> 6) & 31;
        int k   = i >> 11;
        g_W2t[i] = W2[f * (F1 * K2) + fin * K2 + k];
    }
}

// conv2 output GEMM over all k (reads each T2 element once) + bias + relu + maxpool2
// block = one pooled node vp (rows 2vp, 2vp+1); 256 thr: b = tid&63, fg = tid>>6 (16 f each)
__global__ void k_conv2_out(const float* __restrict__ b2) {
    __shared__ alignas(16) float sh[2 * CH2 + F1 * F2];   // T0 | T1 | Wk  (24KB)
    float* sT0 = sh;
    float* sT1 = sh + CH2;
    float* sW  = sh + 2 * CH2;
    int vp = blockIdx.x, tid = threadIdx.x;
    int b = tid & 63, fg = tid >> 6;
    float2 acc0[8], acc1[8];
#pragma unroll
    for (int i = 0; i < 8; i++) { acc0[i] = make_float2(0.f, 0.f); acc1[i] = make_float2(0.f, 0.f); }

    for (int k = 0; k < K2; k++) {
        const float* Tk = g_T2 + (size_t)k * V2n * CH2;
        for (int i = tid; i < CH2; i += 256) {
            sT0[i] = Tk[(size_t)(2 * vp) * CH2 + i];
            sT1[i] = Tk[(size_t)(2 * vp + 1) * CH2 + i];
        }
        for (int i = tid; i < F1 * F2; i += 256) sW[i] = g_W2t[k * (F1 * F2) + i];
        __syncthreads();
#pragma unroll 4
        for (int fin = 0; fin < F1; fin++) {
            float tv0 = sT0[fin * BN + b];
            float tv1 = sT1[fin * BN + b];
            float2 p0 = make_float2(tv0, tv0);
            float2 p1 = make_float2(tv1, tv1);
            const float2* wrow = reinterpret_cast<const float2*>(&sW[fin * F2 + fg * 16]);
#pragma unroll
            for (int j = 0; j < 8; j++) {
                float2 w = wrow[j];
                acc0[j] = ffma2(p0, w, acc0[j]);
                acc1[j] = ffma2(p1, w, acc1[j]);
            }
        }
        __syncthreads();
    }
    // bias + pool + relu, stage in shared, then coalesced store to g_P [b][vp*64+f]
#pragma unroll
    for (int j = 0; j < 8; j++) {
        int f = fg * 16 + 2 * j;
        float bb0 = b2[f], bb1 = b2[f + 1];
        float o0 = fmaxf(fmaxf(acc0[j].x + bb0, acc1[j].x + bb0), 0.f);
        float o1 = fmaxf(fmaxf(acc0[j].y + bb1, acc1[j].y + bb1), 0.f);
        sh[b * 64 + f]     = o0;
        sh[b * 64 + f + 1] = o1;
    }
    __syncthreads();
    for (int o = tid; o < 4096; o += 256) {
        int bb = o >> 6, f = o & 63;
        g_P[(size_t)bb * FC1FIN + vp * 64 + f] = sh[o];
    }
}

// ---------------- FC1: split-K tiled GEMM with f32x2 ----------------
__global__ void k_fc1(const float* __restrict__ W) {
    __shared__ alignas(16) float sP[64 * 34];
    __shared__ alignas(16) float sW[64 * 34];
    int bid = blockIdx.x;
    int jt = bid & 7;          // 8 j-tiles of 64
    int ks = bid >> 3;         // 32 splits of the 65536 reduction (2048 each)
    int tid = threadIdx.x;
    int jq = tid & 15, bq = tid >> 4;
    float2 acc[4][4];
#pragma unroll
    for (int u = 0; u < 4; u++)
#pragma unroll
        for (int w = 0; w < 4; w++) acc[u][w] = make_float2(0.f, 0.f);

    int ibase0 = ks * (FC1FIN / KSPLIT);
    for (int it = 0; it < FC1FIN / KSPLIT; it += 32) {
        int ib = ibase0 + it;
        for (int o = tid; o < 64 * 32; o += 256) {
            int r = o >> 5, i = o & 31;
            sP[r * 34 + i] = g_P[(size_t)r * FC1FIN + ib + i];
            sW[r * 34 + i] = W[(size_t)(jt * 64 + r) * FC1FIN + ib + i];
        }
        __syncthreads();
#pragma unroll
        for (int i = 0; i < 32; i += 2) {
            float2 pv[4], wv[4];
#pragma unroll
            for (int u = 0; u < 4; u++)
                pv[u] = *reinterpret_cast<const float2*>(&sP[(bq * 4 + u) * 34 + i]);
#pragma unroll
            for (int u = 0; u < 4; u++)
                wv[u] = *reinterpret_cast<const float2*>(&sW[(jq * 4 + u) * 34 + i]);
#pragma unroll
            for (int u = 0; u < 4; u++)
#pragma unroll
                for (int w = 0; w < 4; w++)
                    acc[u][w] = ffma2(pv[u], wv[w], acc[u][w]);
        }
        __syncthreads();
    }
#pragma unroll
    for (int u = 0; u < 4; u++)
#pragma unroll
        for (int w = 0; w < 4; w++) {
            float s = acc[u][w].x + acc[u][w].y;
            int b = bq * 4 + u;
            int j = jt * 64 + jq * 4 + w;
            g_fc1p[(size_t)ks * (BN * FC1F) + b * FC1F + j] = s;
        }
}

__global__ void k_fc1_red(const float* __restrict__ b1) {
    int idx = blockIdx.x * blockDim.x + threadIdx.x;   // 32768
    float s = 0.f;
#pragma unroll
    for (int ks = 0; ks < KSPLIT; ks++) s += g_fc1p[ks * (BN * FC1F) + idx];
    int j = idx & 511;
    g_fc1[idx] = fmaxf(s + b1[j], 0.f);
}

// ---------------- FC2 ----------------
__global__ void k_fc2(const float* __restrict__ W, const float* __restrict__ bb,
                      float* __restrict__ out) {
    __shared__ float sf[FC1F];
    int b = blockIdx.x;
    int tid = threadIdx.x;
    for (int j = tid; j < FC1F; j += 320) sf[j] = g_fc1[b * FC1F + j];
    __syncthreads();
    int w = tid >> 5, lane = tid & 31;
    if (w < FC2F) {
        float s = 0.f;
        for (int j = lane; j < FC1F; j += 32) s = fmaf(sf[j], W[w * FC1F + j], s);
#pragma unroll
        for (int off = 16; off; off >>= 1) s += __shfl_down_sync(0xffffffff, s, off);
        if (lane == 0) out[b * FC2F + w] = s + bb[w];
    }
}

// ---------------- launch ----------------
extern "C" void kernel_launch(void* const* d_in, const int* in_sizes, int n_in,
                              void* d_out, int out_size) {
    const float* x    = (const float*)d_in[0];
    const int*   l1r  = (const int*)  d_in[1];
    const int*   l1c  = (const int*)  d_in[2];
    const float* l1v  = (const float*)d_in[3];
    const int*   l2r  = (const int*)  d_in[4];
    const int*   l2c  = (const int*)  d_in[5];
    const float* l2v  = (const float*)d_in[6];
    const float* cl1W = (const float*)d_in[7];
    const float* cl1b = (const float*)d_in[8];
    const float* cl2W = (const float*)d_in[9];
    const float* cl2b = (const float*)d_in[10];
    const float* fc1W = (const float*)d_in[11];
    const float* fc1b = (const float*)d_in[12];
    const float* fc2W = (const float*)d_in[13];
    const float* fc2b = (const float*)d_in[14];
    float* out = (float*)d_out;

    // CSR build (both graphs)
    k_zero<<<16, 256>>>();
    k_count<<<128, 256>>>(l1r, l2r);
    k_scan<<<1, 1024>>>(0);
    k_scan<<<1, 1024>>>(1);
    k_scatter<<<128, 256>>>(l1r, l1c, l1v, NNZ1, 0);
    k_scatter<<<64, 256>>>(l2r, l2c, l2v, NNZ2, 1);

    // conv1
    k_t1_init<<<1024, 256>>>(x);
    for (int k = 1; k < K1; k++) k_cheb1<<<1024, 256>>>(k);
    k_conv1_out<<<512, 256>>>(cl1W, cl1b);

    // conv2
    k_w2t<<<200, 256>>>(cl2W);
    for (int k = 1; k < K2; k++) k_cheb2<<<2048, 256>>>(k);
    k_conv2_out<<<1024, 256>>>(cl2b);

    // FC head
    k_fc1<<<256, 256>>>(fc1W);
    k_fc1_red<<<128, 256>>>(fc1b);
    k_fc2<<<64, 320>>>(fc2W, fc2b, out);
}

// round 5
// speedup vs baseline: 1.0053x; 1.0053x over previous
#include <cuda_runtime.h>

// ---------------- problem constants ----------------
#define D1     4096     // V of graph 1
#define V2n    2048     // V of graph 2
#define BN     64       // batch
#define K1     25
#define K2     25
#define F1     32       // CL1_F
#define F2     64       // CL2_F
#define NNZ1   32768
#define NNZ2   16384
#define CH2    2048     // F1*BN columns of conv2 state
#define FC1F   512
#define FC2F   10
#define FC1FIN 65536    // F2 * (D1/4)
#define KSPLIT 32       // split-K for fc1
// coef = 2/lmax = 1.0 exactly (folded into the math below)

// ---------------- device scratch (static; no runtime alloc) ----------------
__device__ int   g_cnt1[D1];
__device__ int   g_rp1[D1 + 1];
__device__ int   g_cur1[D1];
__device__ int   g_ci1[NNZ1];
__device__ float g_cv1[NNZ1];

__device__ int   g_cnt2[V2n];
__device__ int   g_rp2[V2n + 1];
__device__ int   g_cur2[V2n];
__device__ int   g_ci2[NNZ2];
__device__ float g_cv2[NNZ2];

__device__ float g_T1[K1 * D1 * BN];            // 6.55M floats, Cheby states conv1 [k][v][b]
__device__ float g_T2[K2 * V2n * CH2];          // 104.86M floats (400MB), conv2 states [k][v][fin*64+b]
__device__ float g_W2t[K2 * F1 * F2];           // transposed cl2_W: [k][fin][f]
__device__ float g_P[BN * FC1FIN];              // pooled conv2 out, [b][vp*64+f]
__device__ float g_fc1p[KSPLIT * BN * FC1F];    // fc1 split-K partials
__device__ float g_fc1[BN * FC1F];              // fc1 output (post relu)

// ---------------- f32x2 packed FMA (Blackwell FFMA2, PTX-only) ----------------
__device__ __forceinline__ float2 ffma2(float2 a, float2 b, float2 c) {
    float2 d;
    asm("fma.rn.f32x2 %0, %1, %2, %3;"
        : "=l"(reinterpret_cast<unsigned long long&>(d))
        : "l"(reinterpret_cast<unsigned long long&>(a)),
          "l"(reinterpret_cast<unsigned long long&>(b)),
          "l"(reinterpret_cast<unsigned long long&>(c)));
    return d;
}

// ---------------- CSR build ----------------
__global__ void k_zero() {
    int i = blockIdx.x * blockDim.x + threadIdx.x;
    if (i < D1)  g_cnt1[i] = 0;
    if (i < V2n) g_cnt2[i] = 0;
}

__global__ void k_count(const int* __restrict__ r1, const int* __restrict__ r2) {
    int i = blockIdx.x * blockDim.x + threadIdx.x;
    if (i < NNZ1) atomicAdd(&g_cnt1[r1[i]], 1);
    if (i < NNZ2) atomicAdd(&g_cnt2[r2[i]], 1);
}

__global__ void k_scan(int which) {
    __shared__ int s[1024];
    const int* cnt = which ? g_cnt2 : g_cnt1;
    int V  = which ? V2n : D1;
    int* rp  = which ? g_rp2  : g_rp1;
    int* cur = which ? g_cur2 : g_cur1;
    int tid = threadIdx.x;
    int per = V >> 10;          // 4 (graph1) or 2 (graph2)
    int base = tid * per;
    int loc[4];
    int sum = 0;
    for (int i = 0; i < per; i++) { loc[i] = cnt[base + i]; sum += loc[i]; }
    s[tid] = sum; __syncthreads();
    for (int off = 1; off < 1024; off <<= 1) {
        int v = (tid >= off) ? s[tid - off] : 0;
        __syncthreads();
        s[tid] += v;
        __syncthreads();
    }
    int run = (tid == 0) ? 0 : s[tid - 1];
    for (int i = 0; i < per; i++) { rp[base + i] = run; cur[base + i] = run; run += loc[i]; }
    if (tid == 1023) rp[V] = run;
}

__global__ void k_scatter(const int* __restrict__ rows, const int* __restrict__ cols,
                          const float* __restrict__ vals, int nnz, int which) {
    int i = blockIdx.x * blockDim.x + threadIdx.x;
    if (i >= nnz) return;
    int* cur  = which ? g_cur2 : g_cur1;
    int* ci   = which ? g_ci2  : g_ci1;
    float* cv = which ? g_cv2  : g_cv1;
    int p = atomicAdd(&cur[rows[i]], 1);
    ci[p] = cols[i];
    cv[p] = vals[i];
}

// ---------------- conv1: Chebyshev recurrence on [4096 x 64] ----------------
__global__ void k_t1_init(const float* __restrict__ x) {
    int idx = blockIdx.x * blockDim.x + threadIdx.x;   // < D1*BN
    int v = idx >> 6, b = idx & 63;
    g_T1[idx] = x[b * D1 + v];                          // x0[v][b] = x[b][v][0]
}

__global__ void k_cheb1(int k) {
    int tid = threadIdx.x;
    int v = blockIdx.x * 4 + (tid >> 6);
    int b = tid & 63;
    const float* Tm1 = g_T1 + (k - 1) * (D1 * BN);
    float acc = 0.f;
    int e1 = g_rp1[v + 1];
    for (int e = g_rp1[v]; e < e1; e++)
        acc = fmaf(g_cv1[e], Tm1[g_ci1[e] * BN + b], acc);
    float ls = acc - Tm1[v * BN + b];                   // coef = 1
    float out = (k >= 2) ? (2.f * ls - g_T1[(k - 2) * (D1 * BN) + v * BN + b]) : ls;
    g_T1[k * (D1 * BN) + v * BN + b] = out;
}

// conv1 GEMM (W1 [32,25]) + bias + relu + maxpool2 -> writes T2 slice 0 in [v2][fin*64+b] layout
__global__ void k_conv1_out(const float* __restrict__ W1, const float* __restrict__ b1) {
    __shared__ float sW[F1 * K1];
    __shared__ float sb[F1];
    int tid = threadIdx.x;
    for (int i = tid; i < F1 * K1; i += 256) sW[i] = W1[i];
    if (tid < F1) sb[tid] = b1[tid];
    __syncthreads();
    int v2 = blockIdx.x * 4 + (tid >> 6);
    int b  = tid & 63;
    float t0[K1], t1[K1];
#pragma unroll
    for (int k = 0; k < K1; k++) {
        t0[k] = g_T1[k * (D1 * BN) + (2 * v2) * BN + b];
        t1[k] = g_T1[k * (D1 * BN) + (2 * v2 + 1) * BN + b];
    }
    for (int f = 0; f < F1; f++) {
        float a0 = sb[f], a1 = sb[f];
#pragma unroll
        for (int k = 0; k < K1; k++) {
            float w = sW[f * K1 + k];
            a0 = fmaf(t0[k], w, a0);
            a1 = fmaf(t1[k], w, a1);
        }
        float o = fmaxf(fmaxf(a0, a1), 0.f);
        g_T2[v2 * CH2 + f * BN + b] = o;
    }
}

// ---------------- conv2: Chebyshev recurrence on [2048 x 2048] ----------------
__global__ void k_cheb2(int k) {
    __shared__ int   sci[128];
    __shared__ float scv[128];
    int v = blockIdx.x, tid = threadIdx.x;
    const float* Tm1 = g_T2 + (size_t)(k - 1) * V2n * CH2;
    float* out = g_T2 + (size_t)k * V2n * CH2 + (size_t)v * CH2;
    float acc[8] = {0.f, 0.f, 0.f, 0.f, 0.f, 0.f, 0.f, 0.f};
    int e0 = g_rp2[v], e1 = g_rp2[v + 1];
    for (int eb = e0; eb < e1; eb += 128) {
        int n = min(128, e1 - eb);
        if (tid < n) { sci[tid] = g_ci2[eb + tid]; scv[tid] = g_cv2[eb + tid]; }
        __syncthreads();
        for (int j = 0; j < n; j++) {
            const float* zr = Tm1 + (size_t)sci[j] * CH2 + tid;
            float w = scv[j];
#pragma unroll
            for (int i = 0; i < 8; i++) acc[i] = fmaf(w, zr[i * 256], acc[i]);
        }
        __syncthreads();
    }
    const float* z1r = Tm1 + (size_t)v * CH2;
    if (k >= 2) {
        const float* z0r = g_T2 + (size_t)(k - 2) * V2n * CH2 + (size_t)v * CH2;
#pragma unroll
        for (int i = 0; i < 8; i++) {
            int c = tid + i * 256;
            out[c] = 2.f * (acc[i] - z1r[c]) - z0r[c];
        }
    } else {
#pragma unroll
        for (int i = 0; i < 8; i++) {
            int c = tid + i * 256;
            out[c] = acc[i] - z1r[c];
        }
    }
}

// transpose cl2_W [64][fin*25+k] -> g_W2t[k][fin][f]
__global__ void k_w2t(const float* __restrict__ W2) {
    int i = blockIdx.x * blockDim.x + threadIdx.x;
    if (i < K2 * F1 * F2) {
        int f   = i & 63;
        int fin = (i >> 6) & 31;
        int k   = i >> 11;
        g_W2t[i] = W2[f * (F1 * K2) + fin * K2 + k];
    }
}

// conv2 output GEMM over all k (reads each T2 element once) + bias + relu + maxpool2
// block = one pooled node vp (rows 2vp, 2vp+1); 256 thr: b = tid&63, fg = tid>>6 (16 f each)
__global__ void k_conv2_out(const float* __restrict__ b2) {
    __shared__ alignas(16) float sh[2 * CH2 + F1 * F2];   // T0 | T1 | Wk  (24KB)
    float* sT0 = sh;
    float* sT1 = sh + CH2;
    float* sW  = sh + 2 * CH2;
    int vp = blockIdx.x, tid = threadIdx.x;
    int b = tid & 63, fg = tid >> 6;
    float2 acc0[8], acc1[8];
#pragma unroll
    for (int i = 0; i < 8; i++) { acc0[i] = make_float2(0.f, 0.f); acc1[i] = make_float2(0.f, 0.f); }

    for (int k = 0; k < K2; k++) {
        const float* Tk = g_T2 + (size_t)k * V2n * CH2;
        for (int i = tid; i < CH2; i += 256) {
            sT0[i] = Tk[(size_t)(2 * vp) * CH2 + i];
            sT1[i] = Tk[(size_t)(2 * vp + 1) * CH2 + i];
        }
        for (int i = tid; i < F1 * F2; i += 256) sW[i] = g_W2t[k * (F1 * F2) + i];
        __syncthreads();
#pragma unroll 4
        for (int fin = 0; fin < F1; fin++) {
            float tv0 = sT0[fin * BN + b];
            float tv1 = sT1[fin * BN + b];
            float2 p0 = make_float2(tv0, tv0);
            float2 p1 = make_float2(tv1, tv1);
            const float2* wrow = reinterpret_cast<const float2*>(&sW[fin * F2 + fg * 16]);
#pragma unroll
            for (int j = 0; j < 8; j++) {
                float2 w = wrow[j];
                acc0[j] = ffma2(p0, w, acc0[j]);
                acc1[j] = ffma2(p1, w, acc1[j]);
            }
        }
        __syncthreads();
    }
    // bias + pool + relu, stage in shared, then coalesced store to g_P [b][vp*64+f]
#pragma unroll
    for (int j = 0; j < 8; j++) {
        int f = fg * 16 + 2 * j;
        float bb0 = b2[f], bb1 = b2[f + 1];
        float o0 = fmaxf(fmaxf(acc0[j].x + bb0, acc1[j].x + bb0), 0.f);
        float o1 = fmaxf(fmaxf(acc0[j].y + bb1, acc1[j].y + bb1), 0.f);
        sh[b * 64 + f]     = o0;
        sh[b * 64 + f + 1] = o1;
    }
    __syncthreads();
    for (int o = tid; o < 4096; o += 256) {
        int bb = o >> 6, f = o & 63;
        g_P[(size_t)bb * FC1FIN + vp * 64 + f] = sh[o];
    }
}

// ---------------- FC1: split-K tiled GEMM with f32x2 ----------------
__global__ void k_fc1(const float* __restrict__ W) {
    __shared__ alignas(16) float sP[64 * 34];
    __shared__ alignas(16) float sW[64 * 34];
    int bid = blockIdx.x;
    int jt = bid & 7;          // 8 j-tiles of 64
    int ks = bid >> 3;         // 32 splits of the 65536 reduction (2048 each)
    int tid = threadIdx.x;
    int jq = tid & 15, bq = tid >> 4;
    float2 acc[4][4];
#pragma unroll
    for (int u = 0; u < 4; u++)
#pragma unroll
        for (int w = 0; w < 4; w++) acc[u][w] = make_float2(0.f, 0.f);

    int ibase0 = ks * (FC1FIN / KSPLIT);
    for (int it = 0; it < FC1FIN / KSPLIT; it += 32) {
        int ib = ibase0 + it;
        for (int o = tid; o < 64 * 32; o += 256) {
            int r = o >> 5, i = o & 31;
            sP[r * 34 + i] = g_P[(size_t)r * FC1FIN + ib + i];
            sW[r * 34 + i] = W[(size_t)(jt * 64 + r) * FC1FIN + ib + i];
        }
        __syncthreads();
#pragma unroll
        for (int i = 0; i < 32; i += 2) {
            float2 pv[4], wv[4];
#pragma unroll
            for (int u = 0; u < 4; u++)
                pv[u] = *reinterpret_cast<const float2*>(&sP[(bq * 4 + u) * 34 + i]);
#pragma unroll
            for (int u = 0; u < 4; u++)
                wv[u] = *reinterpret_cast<const float2*>(&sW[(jq * 4 + u) * 34 + i]);
#pragma unroll
            for (int u = 0; u < 4; u++)
#pragma unroll
                for (int w = 0; w < 4; w++)
                    acc[u][w] = ffma2(pv[u], wv[w], acc[u][w]);
        }
        __syncthreads();
    }
#pragma unroll
    for (int u = 0; u < 4; u++)
#pragma unroll
        for (int w = 0; w < 4; w++) {
            float s = acc[u][w].x + acc[u][w].y;
            int b = bq * 4 + u;
            int j = jt * 64 + jq * 4 + w;
            g_fc1p[(size_t)ks * (BN * FC1F) + b * FC1F + j] = s;
        }
}

__global__ void k_fc1_red(const float* __restrict__ b1) {
    int idx = blockIdx.x * blockDim.x + threadIdx.x;   // 32768
    float s = 0.f;
#pragma unroll
    for (int ks = 0; ks < KSPLIT; ks++) s += g_fc1p[ks * (BN * FC1F) + idx];
    int j = idx & 511;
    g_fc1[idx] = fmaxf(s + b1[j], 0.f);
}

// ---------------- FC2 ----------------
__global__ void k_fc2(const float* __restrict__ W, const float* __restrict__ bb,
                      float* __restrict__ out) {
    __shared__ float sf[FC1F];
    int b = blockIdx.x;
    int tid = threadIdx.x;
    for (int j = tid; j < FC1F; j += 320) sf[j] = g_fc1[b * FC1F + j];
    __syncthreads();
    int w = tid >> 5, lane = tid & 31;
    if (w < FC2F) {
        float s = 0.f;
        for (int j = lane; j < FC1F; j += 32) s = fmaf(sf[j], W[w * FC1F + j], s);
#pragma unroll
        for (int off = 16; off; off >>= 1) s += __shfl_down_sync(0xffffffff, s, off);
        if (lane == 0) out[b * FC2F + w] = s + bb[w];
    }
}

// ---------------- launch ----------------
extern "C" void kernel_launch(void* const* d_in, const int* in_sizes, int n_in,
                              void* d_out, int out_size) {
    const float* x    = (const float*)d_in[0];
    const int*   l1r  = (const int*)  d_in[1];
    const int*   l1c  = (const int*)  d_in[2];
    const float* l1v  = (const float*)d_in[3];
    const int*   l2r  = (const int*)  d_in[4];
    const int*   l2c  = (const int*)  d_in[5];
    const float* l2v  = (const float*)d_in[6];
    const float* cl1W = (const float*)d_in[7];
    const float* cl1b = (const float*)d_in[8];
    const float* cl2W = (const float*)d_in[9];
    const float* cl2b = (const float*)d_in[10];
    const float* fc1W = (const float*)d_in[11];
    const float* fc1b = (const float*)d_in[12];
    const float* fc2W = (const float*)d_in[13];
    const float* fc2b = (const float*)d_in[14];
    float* out = (float*)d_out;

    // CSR build (both graphs)
    k_zero<<<16, 256>>>();
    k_count<<<128, 256>>>(l1r, l2r);
    k_scan<<<1, 1024>>>(0);
    k_scan<<<1, 1024>>>(1);
    k_scatter<<<128, 256>>>(l1r, l1c, l1v, NNZ1, 0);
    k_scatter<<<64, 256>>>(l2r, l2c, l2v, NNZ2, 1);

    // conv1
    k_t1_init<<<1024, 256>>>(x);
    for (int k = 1; k < K1; k++) k_cheb1<<<1024, 256>>>(k);
    k_conv1_out<<<512, 256>>>(cl1W, cl1b);

    // conv2
    k_w2t<<<200, 256>>>(cl2W);
    for (int k = 1; k < K2; k++) k_cheb2<<<2048, 256>>>(k);
    k_conv2_out<<<1024, 256>>>(cl2b);

    // FC head
    k_fc1<<<256, 256>>>(fc1W);
    k_fc1_red<<<128, 256>>>(fc1b);
    k_fc2<<<64, 320>>>(fc2W, fc2b, out);
}